// round 12
// baseline (speedup 1.0000x reference)
#include <cuda_runtime.h>
#include <math.h>

#define N_NODES 20000
#define E_EDGES 640000
#define NHEADS  8
#define ROW     128          // floats per edge in both key and value

// CSR row offsets for the sorted edge_dst array (device scratch — no allocs).
__device__ int g_off[N_NODES + 1];

// Streaming boundary scatter: off[n] = lower_bound(dst, n). One pass over dst.
__global__ void build_offsets_kernel(const int* __restrict__ dst) {
    int i = blockIdx.x * blockDim.x + threadIdx.x;
    if (i >= E_EDGES) return;
    int d    = dst[i];
    int prev = (i == 0) ? -1 : dst[i - 1];
    for (int n = prev + 1; n <= d; ++n) g_off[n] = i;
    if (i == E_EDGES - 1)
        for (int n = d + 1; n <= N_NODES; ++n) g_off[n] = E_EDGES;
}

// Force <=32 regs (65536/2048) so 16 CTAs/SM fit: occupancy is the latency-
// hiding budget for this HBM-streaming kernel.
__global__ __launch_bounds__(128, 16) void attn_se3_kernel(
    const float* __restrict__ key,     // (E, 8, 16)  = E x 128
    const float* __restrict__ q0,      // (N, 32, 1)
    const float* __restrict__ q1,      // (N, 32, 3)
    const float* __restrict__ value,   // (E, 32, 4)  = E x 128
    float* __restrict__ out)           // [N*32] deg-0 part, then [N*32*3] deg-1 part
{
    __shared__ float  q_s[ROW];          // fused query, flat (h*16+d)
    __shared__ float  sred_s[4][NHEADS]; // per-warp head sums
    __shared__ float4 vred_s[4][32];     // per-warp value partials (128 cols)

    const int n    = blockIdx.x;
    const int t    = threadIdx.x;
    const int lane = t & 31;
    const int warp = t >> 5;
    const int hq   = lane >> 2;          // head owned by this lane's quad

    const int start = g_off[n];
    const int deg   = g_off[n + 1] - start;

    // Load fused query: q_flat[f] with f = c*4+dv; dv==0 -> query_0, else query_1.
    {
        int c = t >> 2, dv = t & 3;
        q_s[t] = (dv == 0) ? q0[n * 32 + c]
                           : q1[(n * 32 + c) * 3 + (dv - 1)];
    }
    __syncthreads();

    // key flat layout matches q_s flat layout: lane l covers q_s[4l..4l+3].
    const float4 qv = *reinterpret_cast<const float4*>(q_s + lane * 4);

    // Fused mainloop: warp per edge. After the quad shfl-reduce, EVERY lane of
    // a quad holds that head's full 16-dim dot product, so the softmax weight
    // for this lane's value columns (4l..4l+3, same head) is available
    // in-register — no smem weights, no phase barrier.
    const float* kb = key   + (size_t)start * ROW + lane * 4;
    const float* vb = value + (size_t)start * ROW + lane * 4;

    float4 acc  = make_float4(0.f, 0.f, 0.f, 0.f);
    float  hsum = 0.f;                   // identical across the 4 lanes of a quad

    #pragma unroll 4
    for (int el = warp; el < deg; el += 4) {
        const float4 kv = *reinterpret_cast<const float4*>(kb + el * ROW);
        const float4 v  = *reinterpret_cast<const float4*>(vb + el * ROW);
        float d = kv.x * qv.x + kv.y * qv.y + kv.z * qv.z + kv.w * qv.w;
        d += __shfl_xor_sync(0xffffffffu, d, 1);
        d += __shfl_xor_sync(0xffffffffu, d, 2);
        const float ex = __expf(d * 0.08838834764831843f);   // 1/sqrt(128)
        hsum  += ex;
        acc.x += ex * v.x; acc.y += ex * v.y;
        acc.z += ex * v.z; acc.w += ex * v.w;
    }

    // ---- cross-warp reduction
    vred_s[warp][lane] = acc;
    if ((lane & 3) == 0) sred_s[warp][hq] = hsum;
    __syncthreads();

    const int   h   = t >> 4;            // head of output column t
    const float den = sred_s[0][h] + sred_s[1][h] + sred_s[2][h] + sred_s[3][h];
    const float* vr = reinterpret_cast<const float*>(vred_s);
    float v = vr[0 * ROW + t] + vr[1 * ROW + t] + vr[2 * ROW + t] + vr[3 * ROW + t];
    v = (deg > 0) ? v / den : 0.f;

    const int c = t >> 2, dv = t & 3;
    if (dv == 0) out[n * 32 + c] = v;
    else         out[N_NODES * 32 + (n * 32 + c) * 3 + (dv - 1)] = v;
}

extern "C" void kernel_launch(void* const* d_in, const int* in_sizes, int n_in,
                              void* d_out, int out_size) {
    const float* key   = (const float*)d_in[0];   // (E, 8, 16)
    const float* q0    = (const float*)d_in[1];   // (N, 32, 1)
    const float* q1    = (const float*)d_in[2];   // (N, 32, 3)
    const float* value = (const float*)d_in[3];   // (E, 32, 4)
    const int*   dst   = (const int*)d_in[4];     // (E,) sorted
    float* out = (float*)d_out;

    build_offsets_kernel<<<(E_EDGES + 511) / 512, 512>>>(dst);
    attn_se3_kernel<<<N_NODES, 128>>>(key, q0, q1, value, out);
}

// round 13
// speedup vs baseline: 1.0640x; 1.0640x over previous
#include <cuda_runtime.h>
#include <math.h>

#define N_NODES 20000
#define E_EDGES 640000
#define NHEADS  8
#define ROW     128          // floats per edge in both key and value

// CSR row offsets for the sorted edge_dst array (device scratch — no allocs).
__device__ int g_off[N_NODES + 1];

// Streaming boundary scatter: off[n] = lower_bound(dst, n).
// One thread per 4 edges (int4), boundary via one scalar load.
__global__ void build_offsets_kernel(const int* __restrict__ dst) {
    const int i = blockIdx.x * blockDim.x + threadIdx.x;   // quad index
    if (i >= E_EDGES / 4) return;
    const int4 d4 = reinterpret_cast<const int4*>(dst)[i];
    int prev = (i == 0) ? -1 : __ldg(dst + 4 * i - 1);
    const int v[4] = {d4.x, d4.y, d4.z, d4.w};
    #pragma unroll
    for (int k = 0; k < 4; ++k) {
        for (int n = prev + 1; n <= v[k]; ++n) g_off[n] = 4 * i + k;
        prev = v[k];
    }
    if (i == E_EDGES / 4 - 1)
        for (int n = prev + 1; n <= N_NODES; ++n) g_off[n] = E_EDGES;
}

__global__ __launch_bounds__(128) void attn_se3_kernel(
    const float* __restrict__ key,     // (E, 8, 16)  = E x 128
    const float* __restrict__ q0,      // (N, 32, 1)
    const float* __restrict__ q1,      // (N, 32, 3)
    const float* __restrict__ value,   // (E, 32, 4)  = E x 128
    float* __restrict__ out)           // [N*32] deg-0 part, then [N*32*3] deg-1 part
{
    __shared__ float  q_s[ROW];          // fused query, flat (h*16+d)
    __shared__ float  sred_s[4][NHEADS]; // per-warp head sums
    __shared__ float4 vred_s[4][32];     // per-warp value partials (128 cols)

    const int n    = blockIdx.x;
    const int t    = threadIdx.x;
    const int lane = t & 31;
    const int warp = t >> 5;
    const int hq   = lane >> 2;          // head owned by this lane's quad

    const int start = g_off[n];
    const int deg   = g_off[n + 1] - start;

    // Load fused query: q_flat[f] with f = c*4+dv; dv==0 -> query_0, else query_1.
    {
        int c = t >> 2, dv = t & 3;
        q_s[t] = (dv == 0) ? q0[n * 32 + c]
                           : q1[(n * 32 + c) * 3 + (dv - 1)];
    }
    __syncthreads();

    // key flat layout matches q_s flat layout: lane l covers q_s[4l..4l+3].
    const float4 qv = *reinterpret_cast<const float4*>(q_s + lane * 4);

    // Fused mainloop: warp per edge. After the quad shfl-reduce, EVERY lane of
    // a quad holds that head's full 16-dim dot product, so the softmax weight
    // for this lane's value columns (4l..4l+3, same head) is available
    // in-register — no smem weights, no phase barrier.
    const float* kb = key   + (size_t)start * ROW + lane * 4;
    const float* vb = value + (size_t)start * ROW + lane * 4;

    float4 acc  = make_float4(0.f, 0.f, 0.f, 0.f);
    float  hsum = 0.f;                   // identical across the 4 lanes of a quad

    #pragma unroll 4
    for (int el = warp; el < deg; el += 4) {
        const float4 kv = __ldcs(reinterpret_cast<const float4*>(kb + el * ROW));
        const float4 v  = __ldcs(reinterpret_cast<const float4*>(vb + el * ROW));
        float d = kv.x * qv.x + kv.y * qv.y + kv.z * qv.z + kv.w * qv.w;
        d += __shfl_xor_sync(0xffffffffu, d, 1);
        d += __shfl_xor_sync(0xffffffffu, d, 2);
        const float ex = __expf(d * 0.08838834764831843f);   // 1/sqrt(128)
        hsum  += ex;
        acc.x += ex * v.x; acc.y += ex * v.y;
        acc.z += ex * v.z; acc.w += ex * v.w;
    }

    // ---- cross-warp reduction
    vred_s[warp][lane] = acc;
    if ((lane & 3) == 0) sred_s[warp][hq] = hsum;
    __syncthreads();

    const int   h   = t >> 4;            // head of output column t
    const float den = sred_s[0][h] + sred_s[1][h] + sred_s[2][h] + sred_s[3][h];
    const float* vr = reinterpret_cast<const float*>(vred_s);
    float v = vr[0 * ROW + t] + vr[1 * ROW + t] + vr[2 * ROW + t] + vr[3 * ROW + t];
    v = (deg > 0) ? v / den : 0.f;

    const int c = t >> 2, dv = t & 3;
    if (dv == 0) out[n * 32 + c] = v;
    else         out[N_NODES * 32 + (n * 32 + c) * 3 + (dv - 1)] = v;
}

extern "C" void kernel_launch(void* const* d_in, const int* in_sizes, int n_in,
                              void* d_out, int out_size) {
    const float* key   = (const float*)d_in[0];   // (E, 8, 16)
    const float* q0    = (const float*)d_in[1];   // (N, 32, 1)
    const float* q1    = (const float*)d_in[2];   // (N, 32, 3)
    const float* value = (const float*)d_in[3];   // (E, 32, 4)
    const int*   dst   = (const int*)d_in[4];     // (E,) sorted
    float* out = (float*)d_out;

    build_offsets_kernel<<<(E_EDGES / 4 + 255) / 256, 256>>>(dst);
    attn_se3_kernel<<<N_NODES, 128>>>(key, q0, q1, value, out);
}